// round 3
// baseline (speedup 1.0000x reference)
#include <cuda_runtime.h>
#include <math.h>

#define BATCH 4
#define SEQ   2048
#define FD    128
#define HEADS 4
#define TM    64
#define TN    64

#define S1_STRIDE 132   // padded stride for 64x128 fp32 tiles (float4-aligned, bank-split)
#define QS_STRIDE 132
#define XP_STRIDE 129   // odd-ish stride: conflict-free scalar access in both GEMM directions

// Scratch (allocation-free rule: __device__ globals)
__device__ float g_Xp[BATCH*SEQ*FD];          // 4 MB
__device__ float g_Q [BATCH*HEADS*SEQ*FD];    // 16 MB

// C[64][128] = A[64][128] @ W[128][128], A in smem (stride S1_STRIDE), W in smem (stride 128).
// Thread (ty = t>>4, tx = t&15): rows 4*ty..+3, cols tx + 16*jj (jj<8).
__device__ __forceinline__ void gemm_tile_64x128(
    const float* __restrict__ Asrc,
    const float* __restrict__ Wsrc,
    int ty, int tx, float acc[4][8])
{
#pragma unroll
    for (int i = 0; i < 4; i++)
#pragma unroll
        for (int jj = 0; jj < 8; jj++) acc[i][jj] = 0.f;

#pragma unroll 2
    for (int k = 0; k < FD; k += 4) {
        float a[4][4];
#pragma unroll
        for (int i = 0; i < 4; i++) {
            float4 v = *(const float4*)(Asrc + (4*ty + i)*S1_STRIDE + k);
            a[i][0] = v.x; a[i][1] = v.y; a[i][2] = v.z; a[i][3] = v.w;
        }
#pragma unroll
        for (int kk = 0; kk < 4; kk++) {
            float w[8];
#pragma unroll
            for (int jj = 0; jj < 8; jj++)
                w[jj] = Wsrc[(k + kk)*FD + tx + 16*jj];
#pragma unroll
            for (int i = 0; i < 4; i++)
#pragma unroll
                for (int jj = 0; jj < 8; jj++)
                    acc[i][jj] = fmaf(a[i][kk], w[jj], acc[i][jj]);
        }
    }
}

// ---------------- Stage 1: Xp = X@W + bias; Q_h = Xp@attn_h ----------------
// grid = BATCH * (SEQ/TM) = 128 blocks, 256 threads
extern "C" __global__ void __launch_bounds__(256, 1)
stage1_kernel(const float* __restrict__ X, const float* __restrict__ Wk,
              const float* __restrict__ bias, const float* __restrict__ attn)
{
    extern __shared__ float sm1[];
    float* Xs  = sm1;                         // 64 * 132
    float* Ws  = Xs + TM*S1_STRIDE;           // 128 * 128
    float* Xps = Ws + FD*FD;                  // 64 * 132

    const int t  = threadIdx.x;
    const int b  = blockIdx.x >> 5;
    const int n0 = (blockIdx.x & 31) * TM;
    const int tx = t & 15, ty = t >> 4;

    // Load X tile (64x128)
    {
        const float4* src = (const float4*)(X + (size_t)(b*SEQ + n0)*FD);
#pragma unroll
        for (int i = 0; i < 8; i++) {
            int idx = t + i*256;
            int r = idx >> 5, c4 = idx & 31;
            *(float4*)(Xs + r*S1_STRIDE + 4*c4) = src[idx];
        }
    }
    // Load projection weights (128x128)
    {
        const float4* src = (const float4*)Wk;
#pragma unroll
        for (int i = 0; i < 16; i++)
            ((float4*)Ws)[t + i*256] = src[t + i*256];
    }
    __syncthreads();

    float acc[4][8];
    gemm_tile_64x128(Xs, Ws, ty, tx, acc);

    float bv[8];
#pragma unroll
    for (int jj = 0; jj < 8; jj++) bv[jj] = bias[tx + 16*jj];

#pragma unroll
    for (int i = 0; i < 4; i++) {
        int r = 4*ty + i;
        int n = n0 + r;
#pragma unroll
        for (int jj = 0; jj < 8; jj++) {
            float v = acc[i][jj] + bv[jj];
            Xps[r*S1_STRIDE + tx + 16*jj] = v;                      // smem stage for Q GEMMs
            g_Xp[(size_t)(b*SEQ + n)*FD + tx + 16*jj] = v;          // coalesced (16 consecutive lanes)
        }
    }

    for (int h = 0; h < HEADS; h++) {
        __syncthreads();   // Xps visible; prior Ws readers done
        const float4* src = (const float4*)(attn + (size_t)h*FD*FD);
#pragma unroll
        for (int i = 0; i < 16; i++)
            ((float4*)Ws)[t + i*256] = src[t + i*256];
        __syncthreads();

        float q[4][8];
        gemm_tile_64x128(Xps, Ws, ty, tx, q);
#pragma unroll
        for (int i = 0; i < 4; i++) {
            int n = n0 + 4*ty + i;
            float* dst = g_Q + ((size_t)(b*HEADS + h)*SEQ + n)*FD;
#pragma unroll
            for (int jj = 0; jj < 8; jj++)
                dst[tx + 16*jj] = q[i][jj];
        }
    }
}

// ---------------- Stage 2: fused scores/tanh-mask/aggregate/epilogue ----------------
// grid = BATCH * (SEQ/TM) = 128 blocks, 256 threads, ~196 KB dynamic smem (1 block/SM)
extern "C" __global__ void __launch_bounds__(256, 1)
stage2_kernel(const float* __restrict__ Aadj, const float* __restrict__ X,
              float* __restrict__ out)
{
    extern __shared__ float sm2[];
    float* Qs  = sm2;                         // 4 * 64 * 132  (all 4 heads resident)
    float* Xps = Qs + HEADS*TM*QS_STRIDE;     // 64 * 129
    float* As  = Xps + TN*XP_STRIDE;          // 64 * 64
    float* Ams = As + TM*TN;                  // 64 * 64

    const int t  = threadIdx.x;
    const int b  = blockIdx.x >> 5;
    const int n0 = (blockIdx.x & 31) * TM;
    const int tx = t & 15, ty = t >> 4;

    // Load Q tiles for all 4 heads once (128 KB)
#pragma unroll
    for (int h = 0; h < HEADS; h++) {
        const float4* src = (const float4*)(g_Q + ((size_t)(b*HEADS + h)*SEQ + n0)*FD);
        float* dsth = Qs + h*TM*QS_STRIDE;
#pragma unroll
        for (int i = 0; i < 8; i++) {
            int idx = t + i*256;
            int r = idx >> 5, c4 = idx & 31;
            *(float4*)(dsth + r*QS_STRIDE + 4*c4) = src[idx];
        }
    }

    float O[4][8];
#pragma unroll
    for (int i = 0; i < 4; i++)
#pragma unroll
        for (int jj = 0; jj < 8; jj++) O[i][jj] = 0.f;

    for (int mt = 0; mt < SEQ/TN; mt++) {
        const int m0 = mt * TN;
        __syncthreads();   // previous tile consumers done

        // Load Xp m-tile (scalar STS — stride 129 is not 16B aligned per row)
        {
            const float4* src = (const float4*)(g_Xp + (size_t)(b*SEQ + m0)*FD);
#pragma unroll
            for (int i = 0; i < 8; i++) {
                int idx = t + i*256;
                int r = idx >> 5, c4 = idx & 31;
                float4 v = src[idx];
                float* p = Xps + r*XP_STRIDE + 4*c4;
                p[0] = v.x; p[1] = v.y; p[2] = v.z; p[3] = v.w;
            }
        }
        // Load adjacency tile A[b, n0:n0+64, m0:m0+64]
        {
#pragma unroll
            for (int i = 0; i < 4; i++) {
                int idx = t + i*256;
                int r = idx >> 4, c4 = idx & 15;
                float4 v = *(const float4*)(Aadj + (size_t)(b*SEQ + n0 + r)*SEQ + m0 + 4*c4);
                *(float4*)(As + r*TN + 4*c4) = v;
            }
        }
        __syncthreads();

        for (int h = 0; h < HEADS; h++) {
            // --- S-GEMM: S[n][m] = Q_h[n][:] . Xp[m][:]  (K = 128) ---
            // thread rows n = 4*ty+i, cols m = tx + 16*j
            const float* Qh = Qs + h*TM*QS_STRIDE;
            float S[4][4];
#pragma unroll
            for (int i = 0; i < 4; i++)
#pragma unroll
                for (int j = 0; j < 4; j++) S[i][j] = 0.f;

#pragma unroll 2
            for (int k = 0; k < FD; k += 4) {
                float a[4][4];
#pragma unroll
                for (int i = 0; i < 4; i++) {
                    float4 v = *(const float4*)(Qh + (4*ty + i)*QS_STRIDE + k);
                    a[i][0] = v.x; a[i][1] = v.y; a[i][2] = v.z; a[i][3] = v.w;
                }
                float xb[4][4];
#pragma unroll
                for (int j = 0; j < 4; j++)
#pragma unroll
                    for (int kk = 0; kk < 4; kk++)
                        xb[j][kk] = Xps[(tx + 16*j)*XP_STRIDE + k + kk];
#pragma unroll
                for (int kk = 0; kk < 4; kk++)
#pragma unroll
                    for (int i = 0; i < 4; i++)
#pragma unroll
                        for (int j = 0; j < 4; j++)
                            S[i][j] = fmaf(a[i][kk], xb[j][kk], S[i][j]);
            }

            // --- mask * tanh, stage Am tile to smem ---
#pragma unroll
            for (int i = 0; i < 4; i++)
#pragma unroll
                for (int j = 0; j < 4; j++) {
                    int row = 4*ty + i, col = tx + 16*j;
                    Ams[row*TN + col] = tanhf(As[row*TN + col] * S[i][j]);
                }
            __syncthreads();

            // --- O-GEMM: O[n][d] += Am[n][m] * Xp[m][d]  (K = 64), d = tx + 16*jj ---
#pragma unroll 2
            for (int mk = 0; mk < TN; mk += 4) {
                float am[4][4];
#pragma unroll
                for (int i = 0; i < 4; i++) {
                    float4 v = *(const float4*)(Ams + (4*ty + i)*TN + mk);
                    am[i][0] = v.x; am[i][1] = v.y; am[i][2] = v.z; am[i][3] = v.w;
                }
#pragma unroll
                for (int kk = 0; kk < 4; kk++) {
                    float xv[8];
#pragma unroll
                    for (int jj = 0; jj < 8; jj++)
                        xv[jj] = Xps[(mk + kk)*XP_STRIDE + tx + 16*jj];
#pragma unroll
                    for (int i = 0; i < 4; i++)
#pragma unroll
                        for (int jj = 0; jj < 8; jj++)
                            O[i][jj] = fmaf(am[i][kk], xv[jj], O[i][jj]);
                }
            }
            __syncthreads();   // protect Ams before next head overwrites
        }
    }

    // Epilogue: mean over heads, relu, skip, relu
    const float invH = 1.0f / HEADS;
#pragma unroll
    for (int i = 0; i < 4; i++) {
        int n = n0 + 4*ty + i;
        const float* xrow = X + (size_t)(b*SEQ + n)*FD;
        float* orow = out + (size_t)(b*SEQ + n)*FD;
#pragma unroll
        for (int jj = 0; jj < 8; jj++) {
            int d = tx + 16*jj;
            float xh = fmaxf(O[i][jj] * invH, 0.f);
            orow[d] = fmaxf(xh + xrow[d], 0.f);
        }
    }
}

extern "C" void kernel_launch(void* const* d_in, const int* in_sizes, int n_in,
                              void* d_out, int out_size)
{
    (void)out_size;
    // Identify inputs by element count (all distinct) for robustness.
    const float *X = nullptr, *A = nullptr, *Wk = nullptr, *bias = nullptr, *attn = nullptr;
    for (int i = 0; i < n_in; i++) {
        switch (in_sizes[i]) {
            case BATCH*SEQ*FD:  X    = (const float*)d_in[i]; break;   // 1048576
            case BATCH*SEQ*SEQ: A    = (const float*)d_in[i]; break;   // 16777216
            case FD*FD:         Wk   = (const float*)d_in[i]; break;   // 16384
            case FD:            bias = (const float*)d_in[i]; break;   // 128
            case HEADS*FD*FD:   attn = (const float*)d_in[i]; break;   // 65536
        }
    }

    const int s1_smem = (TM*S1_STRIDE + FD*FD + TM*S1_STRIDE) * (int)sizeof(float);          // 133120
    const int s2_smem = (HEADS*TM*QS_STRIDE + TN*XP_STRIDE + 2*TM*TN) * (int)sizeof(float);  // 200960
    cudaFuncSetAttribute(stage1_kernel, cudaFuncAttributeMaxDynamicSharedMemorySize, s1_smem);
    cudaFuncSetAttribute(stage2_kernel, cudaFuncAttributeMaxDynamicSharedMemorySize, s2_smem);

    stage1_kernel<<<BATCH*(SEQ/TM), 256, s1_smem>>>(X, Wk, bias, attn);
    stage2_kernel<<<BATCH*(SEQ/TM), 256, s2_smem>>>(A, X, (float*)d_out);
}

// round 10
// speedup vs baseline: 2.3719x; 2.3719x over previous
#include <cuda_runtime.h>
#include <cuda_bf16.h>
#include <cstdint>
#include <math.h>

#define BATCH 4
#define SEQ   2048
#define FD    128
#define HEADS 4
#define TM    64
#define S1_STRIDE 132

#define XS     272            // smem row stride in bytes (136 bf16): conflict-free ldmatrix
#define TILE_B (128*XS)       // 34816 B per 128x128 bf16 tile

// ---------------- scratch (__device__ globals; no allocs allowed) ----------------
__device__ __nv_bfloat16 g_Xphi [BATCH*SEQ*FD];
__device__ __nv_bfloat16 g_Xplo [BATCH*SEQ*FD];
__device__ __nv_bfloat16 g_XpThi[BATCH*FD*SEQ];      // [b][d][n]
__device__ __nv_bfloat16 g_XpTlo[BATCH*FD*SEQ];
__device__ __nv_bfloat16 g_Qhi  [BATCH*HEADS*SEQ*FD];
__device__ __nv_bfloat16 g_Qlo  [BATCH*HEADS*SEQ*FD];
__device__ float g_Opart[2*BATCH*SEQ*FD];            // [pair][b][n][d]

__device__ __forceinline__ uint32_t smem_to_u32(const void* p) {
    uint32_t a;
    asm("{ .reg .u64 t; cvta.to.shared.u64 t, %1; cvt.u32.u64 %0, t; }" : "=r"(a) : "l"(p));
    return a;
}

#define LDSM4(r, addr) \
    asm volatile("ldmatrix.sync.aligned.m8n8.x4.shared.b16 {%0,%1,%2,%3}, [%4];" \
        : "=r"((r)[0]), "=r"((r)[1]), "=r"((r)[2]), "=r"((r)[3]) : "r"(addr))

#define MMA(c, a, b0_, b1_) \
    asm volatile("mma.sync.aligned.m16n8k16.row.col.f32.bf16.bf16.f32 " \
        "{%0,%1,%2,%3}, {%4,%5,%6,%7}, {%8,%9}, {%0,%1,%2,%3};" \
        : "+f"((c)[0]), "+f"((c)[1]), "+f"((c)[2]), "+f"((c)[3]) \
        : "r"((a)[0]), "r"((a)[1]), "r"((a)[2]), "r"((a)[3]), "r"(b0_), "r"(b1_))

__device__ __forceinline__ void split_bf16(float v, __nv_bfloat16& hi, __nv_bfloat16& lo) {
    hi = __float2bfloat16(v);
    lo = __float2bfloat16(v - __bfloat162float(hi));
}
__device__ __forceinline__ uint32_t pack2(__nv_bfloat16 a, __nv_bfloat16 b) {
    return (uint32_t)__bfloat16_as_ushort(a) | ((uint32_t)__bfloat16_as_ushort(b) << 16);
}

// gmem [128 x 128] bf16 (row stride ldm elems) -> smem padded rows of XS bytes
__device__ __forceinline__ void load_tile(const __nv_bfloat16* __restrict__ src, int ldm,
                                          char* dst, int t) {
#pragma unroll
    for (int i = 0; i < 8; i++) {
        int idx = t + i*256;
        int r = idx >> 4, c = idx & 15;
        uint4 v = *(const uint4*)(src + (size_t)r*ldm + c*8);
        *(uint4*)(dst + r*XS + c*16) = v;
    }
}

// ---------------- Stage 1 (FFMA): Xp = X@W + b; Q_h = Xp@attn_h; emit bf16 splits ----------------
__device__ __forceinline__ void gemm_tile_64x128(
    const float* __restrict__ Asrc, const float* __restrict__ Wsrc,
    int ty, int tx, float acc[4][8])
{
#pragma unroll
    for (int i = 0; i < 4; i++)
#pragma unroll
        for (int jj = 0; jj < 8; jj++) acc[i][jj] = 0.f;
#pragma unroll 2
    for (int k = 0; k < FD; k += 4) {
        float a[4][4];
#pragma unroll
        for (int i = 0; i < 4; i++) {
            float4 v = *(const float4*)(Asrc + (4*ty + i)*S1_STRIDE + k);
            a[i][0] = v.x; a[i][1] = v.y; a[i][2] = v.z; a[i][3] = v.w;
        }
#pragma unroll
        for (int kk = 0; kk < 4; kk++) {
            float w[8];
#pragma unroll
            for (int jj = 0; jj < 8; jj++) w[jj] = Wsrc[(k + kk)*FD + tx + 16*jj];
#pragma unroll
            for (int i = 0; i < 4; i++)
#pragma unroll
                for (int jj = 0; jj < 8; jj++)
                    acc[i][jj] = fmaf(a[i][kk], w[jj], acc[i][jj]);
        }
    }
}

extern "C" __global__ void __launch_bounds__(256, 1)
stage1_kernel(const float* __restrict__ X, const float* __restrict__ Wk,
              const float* __restrict__ bias, const float* __restrict__ attn)
{
    extern __shared__ float sm1[];
    float* Xs  = sm1;
    float* Ws  = Xs + TM*S1_STRIDE;
    float* Xps = Ws + FD*FD;

    const int t  = threadIdx.x;
    const int b  = blockIdx.x >> 5;
    const int n0 = (blockIdx.x & 31) * TM;
    const int tx = t & 15, ty = t >> 4;

    {
        const float4* src = (const float4*)(X + (size_t)(b*SEQ + n0)*FD);
#pragma unroll
        for (int i = 0; i < 8; i++) {
            int idx = t + i*256;
            int r = idx >> 5, c4 = idx & 31;
            *(float4*)(Xs + r*S1_STRIDE + 4*c4) = src[idx];
        }
    }
    {
        const float4* src = (const float4*)Wk;
#pragma unroll
        for (int i = 0; i < 16; i++) ((float4*)Ws)[t + i*256] = src[t + i*256];
    }
    __syncthreads();

    float acc[4][8];
    gemm_tile_64x128(Xs, Ws, ty, tx, acc);

    float bv[8];
#pragma unroll
    for (int jj = 0; jj < 8; jj++) bv[jj] = bias[tx + 16*jj];

#pragma unroll
    for (int i = 0; i < 4; i++) {
        int r = 4*ty + i, n = n0 + r;
#pragma unroll
        for (int jj = 0; jj < 8; jj++) {
            float v = acc[i][jj] + bv[jj];
            int d = tx + 16*jj;
            Xps[r*S1_STRIDE + d] = v;
            __nv_bfloat16 hi, lo; split_bf16(v, hi, lo);
            size_t gi = (size_t)(b*SEQ + n)*FD + d;
            g_Xphi[gi] = hi; g_Xplo[gi] = lo;
        }
    }
    __syncthreads();

    for (int idx = t; idx < FD*TM; idx += 256) {
        int d = idx >> 6, nn = idx & 63;
        float v = Xps[nn*S1_STRIDE + d];
        __nv_bfloat16 hi, lo; split_bf16(v, hi, lo);
        size_t gi = ((size_t)b*FD + d)*SEQ + n0 + nn;
        g_XpThi[gi] = hi; g_XpTlo[gi] = lo;
    }

    for (int h = 0; h < HEADS; h++) {
        __syncthreads();
        const float4* src = (const float4*)(attn + (size_t)h*FD*FD);
#pragma unroll
        for (int i = 0; i < 16; i++) ((float4*)Ws)[t + i*256] = src[t + i*256];
        __syncthreads();

        float q[4][8];
        gemm_tile_64x128(Xps, Ws, ty, tx, q);
#pragma unroll
        for (int i = 0; i < 4; i++) {
            int n = n0 + 4*ty + i;
#pragma unroll
            for (int jj = 0; jj < 8; jj++) {
                int d = tx + 16*jj;
                __nv_bfloat16 hi, lo; split_bf16(q[i][jj], hi, lo);
                size_t gi = ((size_t)(b*HEADS + h)*SEQ + n)*FD + d;
                g_Qhi[gi] = hi; g_Qlo[gi] = lo;
            }
        }
    }
}

// ---------------- Stage 2 (mma.sync bf16 split-2) ----------------
// grid = 4b * 16 ntiles * 2 head-pairs = 128 CTAs, 256 threads, ~204KB smem
extern "C" __global__ void __launch_bounds__(256, 1)
stage2_kernel(const float* __restrict__ Aadj)
{
    extern __shared__ char sm[];
    char* sQhi = sm;
    char* sQlo = sm + TILE_B;
    char* sThi = sm + 2*TILE_B;    // XpT hi  [d][m]
    char* sTlo = sm + 3*TILE_B;
    char* sPhi = sm + 4*TILE_B;    // Xp hi [m][k]  -> reused as Am hi [n][m]
    char* sPlo = sm + 5*TILE_B;

    const int t = threadIdx.x, w = t >> 5, lane = t & 31;
    const int wM = w & 3, wN = w >> 2;
    const int g = lane >> 2, q = lane & 3;
    const int pair = blockIdx.x & 1;
    const int bnt  = blockIdx.x >> 1;
    const int b    = bnt >> 4;
    const int n0   = (bnt & 15) << 7;

    // ldmatrix per-lane byte offsets (x4, non-trans)
    const int tr = lane & 7, tg = lane >> 3;
    const int a_off = (((tg & 1) << 3) + tr) * XS + (((tg >> 1) & 1) << 3) * 2;  // A: (rowgrp, kgrp)
    const int b_off = ((((tg >> 1) & 1) << 3) + tr) * XS + ((tg & 1) << 3) * 2;  // B: (kgrp, rowgrp)

    const uint32_t uQhi = smem_to_u32(sQhi), uQlo = smem_to_u32(sQlo);
    const uint32_t uThi = smem_to_u32(sThi), uTlo = smem_to_u32(sTlo);
    const uint32_t uPhi = smem_to_u32(sPhi), uPlo = smem_to_u32(sPlo);

    const uint32_t aS_hi = uQhi + (32*wM)*XS + a_off;
    const uint32_t aS_lo = uQlo + (32*wM)*XS + a_off;
    const uint32_t bS_hi = uPhi + (64*wN)*XS + b_off;
    const uint32_t bS_lo = uPlo + (64*wN)*XS + b_off;
    const uint32_t aO_hi = uPhi + (32*wM)*XS + a_off;
    const uint32_t aO_lo = uPlo + (32*wM)*XS + a_off;
    const uint32_t bO_hi = uThi + (64*wN)*XS + b_off;
    const uint32_t bO_lo = uTlo + (64*wN)*XS + b_off;

    float O[2][8][4];
#pragma unroll
    for (int mi = 0; mi < 2; mi++)
#pragma unroll
        for (int nt = 0; nt < 8; nt++)
#pragma unroll
            for (int c = 0; c < 4; c++) O[mi][nt][c] = 0.f;

    for (int hh = 0; hh < 2; hh++) {
        const int h = pair*2 + hh;
        __syncthreads();   // prior readers of Q buffers done
        load_tile(g_Qhi + ((size_t)(b*HEADS + h)*SEQ + n0)*FD, FD, sQhi, t);
        load_tile(g_Qlo + ((size_t)(b*HEADS + h)*SEQ + n0)*FD, FD, sQlo, t);

        for (int mt = 0; mt < 16; mt++) {
            const int m0 = mt << 7;
            __syncthreads();   // prior O-GEMM reads of XpT/Am done; Q visible
            load_tile(g_Xphi  + (size_t)(b*SEQ + m0)*FD, FD, sPhi, t);
            load_tile(g_Xplo  + (size_t)(b*SEQ + m0)*FD, FD, sPlo, t);
            load_tile(g_XpThi + (size_t)b*FD*SEQ + m0, SEQ, sThi, t);
            load_tile(g_XpTlo + (size_t)b*FD*SEQ + m0, SEQ, sTlo, t);
            __syncthreads();

            // ---- S-GEMM: S[n][m] = Q[n][k].Xp[m][k], bf16 split 3-term ----
            float S[2][8][4];
#pragma unroll
            for (int mi = 0; mi < 2; mi++)
#pragma unroll
                for (int nt = 0; nt < 8; nt++)
#pragma unroll
                    for (int c = 0; c < 4; c++) S[mi][nt][c] = 0.f;

#pragma unroll 2
            for (int kc = 0; kc < 8; kc++) {
                uint32_t ah0[4], ah1[4], al0[4], al1[4];
                LDSM4(ah0, aS_hi + kc*32);
                LDSM4(ah1, aS_hi + 16*XS + kc*32);
                LDSM4(al0, aS_lo + kc*32);
                LDSM4(al1, aS_lo + 16*XS + kc*32);
#pragma unroll
                for (int np = 0; np < 4; np++) {
                    uint32_t bh[4], bl[4];
                    LDSM4(bh, bS_hi + np*16*XS + kc*32);
                    LDSM4(bl, bS_lo + np*16*XS + kc*32);
                    MMA(S[0][2*np],   ah0, bh[0], bh[1]);
                    MMA(S[1][2*np],   ah1, bh[0], bh[1]);
                    MMA(S[0][2*np+1], ah0, bh[2], bh[3]);
                    MMA(S[1][2*np+1], ah1, bh[2], bh[3]);
                    MMA(S[0][2*np],   al0, bh[0], bh[1]);
                    MMA(S[1][2*np],   al1, bh[0], bh[1]);
                    MMA(S[0][2*np+1], al0, bh[2], bh[3]);
                    MMA(S[1][2*np+1], al1, bh[2], bh[3]);
                    MMA(S[0][2*np],   ah0, bl[0], bl[1]);
                    MMA(S[1][2*np],   ah1, bl[0], bl[1]);
                    MMA(S[0][2*np+1], ah0, bl[2], bl[3]);
                    MMA(S[1][2*np+1], ah1, bl[2], bl[3]);
                }
            }

            // ---- Am = tanh(A .* S); split to bf16 hi/lo, packed in-place into S regs ----
            const float* abase = Aadj + ((size_t)(b*SEQ) + n0 + 32*wM)*SEQ + m0 + 64*wN;
#pragma unroll
            for (int mi = 0; mi < 2; mi++)
#pragma unroll
                for (int nt = 0; nt < 8; nt++) {
                    const float* p = abase + (size_t)(16*mi + g)*SEQ + 8*nt + 2*q;
                    float2 a01 = *(const float2*)p;
                    float2 a23 = *(const float2*)(p + (size_t)8*SEQ);
                    float v0 = tanhf(a01.x * S[mi][nt][0]);
                    float v1 = tanhf(a01.y * S[mi][nt][1]);
                    float v2 = tanhf(a23.x * S[mi][nt][2]);
                    float v3 = tanhf(a23.y * S[mi][nt][3]);
                    __nv_bfloat16 h0, l0, h1, l1, h2, l2, h3, l3;
                    split_bf16(v0, h0, l0); split_bf16(v1, h1, l1);
                    split_bf16(v2, h2, l2); split_bf16(v3, h3, l3);
                    S[mi][nt][0] = __uint_as_float(pack2(h0, h1));   // hi row g
                    S[mi][nt][1] = __uint_as_float(pack2(l0, l1));   // lo row g
                    S[mi][nt][2] = __uint_as_float(pack2(h2, h3));   // hi row g+8
                    S[mi][nt][3] = __uint_as_float(pack2(l2, l3));   // lo row g+8
                }

            __syncthreads();   // all warps done reading Xp (S-GEMM B) before Am overwrite

#pragma unroll
            for (int mi = 0; mi < 2; mi++)
#pragma unroll
                for (int nt = 0; nt < 8; nt++) {
                    int row = 32*wM + 16*mi + g;
                    int col = 64*wN + 8*nt + 2*q;
                    *(uint32_t*)(sPhi + row*XS + col*2)     = __float_as_uint(S[mi][nt][0]);
                    *(uint32_t*)(sPlo + row*XS + col*2)     = __float_as_uint(S[mi][nt][1]);
                    *(uint32_t*)(sPhi + (row+8)*XS + col*2) = __float_as_uint(S[mi][nt][2]);
                    *(uint32_t*)(sPlo + (row+8)*XS + col*2) = __float_as_uint(S[mi][nt][3]);
                }
            // O-GEMM A-operand rows 32*wM..+31 span ALL 128 m-columns, but this warp
            // only wrote columns 64*wN..+63 — the other half comes from warp (wM, 1-wN).
            // Cross-warp dependency => full CTA barrier (the __syncwarp here was the R8 bug).
            __syncthreads();

            // ---- O-GEMM: O[n][d] += Am[n][m].XpT[d][m], bf16 split 3-term ----
#pragma unroll 2
            for (int kc = 0; kc < 8; kc++) {
                uint32_t ah0[4], ah1[4], al0[4], al1[4];
                LDSM4(ah0, aO_hi + kc*32);
                LDSM4(ah1, aO_hi + 16*XS + kc*32);
                LDSM4(al0, aO_lo + kc*32);
                LDSM4(al1, aO_lo + 16*XS + kc*32);
#pragma unroll
                for (int np = 0; np < 4; np++) {
                    uint32_t bh[4], bl[4];
                    LDSM4(bh, bO_hi + np*16*XS + kc*32);
                    LDSM4(bl, bO_lo + np*16*XS + kc*32);
                    MMA(O[0][2*np],   ah0, bh[0], bh[1]);
                    MMA(O[1][2*np],   ah1, bh[0], bh[1]);
                    MMA(O[0][2*np+1], ah0, bh[2], bh[3]);
                    MMA(O[1][2*np+1], ah1, bh[2], bh[3]);
                    MMA(O[0][2*np],   al0, bh[0], bh[1]);
                    MMA(O[1][2*np],   al1, bh[0], bh[1]);
                    MMA(O[0][2*np+1], al0, bh[2], bh[3]);
                    MMA(O[1][2*np+1], al1, bh[2], bh[3]);
                    MMA(O[0][2*np],   ah0, bl[0], bl[1]);
                    MMA(O[1][2*np],   ah1, bl[0], bl[1]);
                    MMA(O[0][2*np+1], ah0, bl[2], bl[3]);
                    MMA(O[1][2*np+1], ah1, bl[2], bl[3]);
                }
            }
        }
    }

    // ---- epilogue: dump O partial (fp32) ----
    float* dst = g_Opart + (size_t)pair*BATCH*SEQ*FD + ((size_t)(b*SEQ) + n0)*FD;
#pragma unroll
    for (int mi = 0; mi < 2; mi++)
#pragma unroll
        for (int nt = 0; nt < 8; nt++) {
            int row = 32*wM + 16*mi + g;
            int col = 64*wN + 8*nt + 2*q;
            float2 v01 = make_float2(O[mi][nt][0], O[mi][nt][1]);
            float2 v23 = make_float2(O[mi][nt][2], O[mi][nt][3]);
            *(float2*)(dst + (size_t)row*FD + col)     = v01;
            *(float2*)(dst + (size_t)(row+8)*FD + col) = v23;
        }
}

// ---------------- combine: mean over heads, relu, skip, relu ----------------
extern "C" __global__ void __launch_bounds__(256, 1)
combine_kernel(const float4* __restrict__ X, float4* __restrict__ out)
{
    const int i = blockIdx.x * 256 + threadIdx.x;
    const float4* O0 = (const float4*)g_Opart;
    const float4* O1 = O0 + (BATCH*SEQ*FD/4);
    float4 a = O0[i], c = O1[i], x = X[i], r;
    r.x = fmaxf(fmaxf((a.x + c.x) * 0.25f, 0.f) + x.x, 0.f);
    r.y = fmaxf(fmaxf((a.y + c.y) * 0.25f, 0.f) + x.y, 0.f);
    r.z = fmaxf(fmaxf((a.z + c.z) * 0.25f, 0.f) + x.z, 0.f);
    r.w = fmaxf(fmaxf((a.w + c.w) * 0.25f, 0.f) + x.w, 0.f);
    out[i] = r;
}

extern "C" void kernel_launch(void* const* d_in, const int* in_sizes, int n_in,
                              void* d_out, int out_size)
{
    (void)out_size;
    const float *X = nullptr, *A = nullptr, *Wk = nullptr, *bias = nullptr, *attn = nullptr;
    for (int i = 0; i < n_in; i++) {
        switch (in_sizes[i]) {
            case BATCH*SEQ*FD:  X    = (const float*)d_in[i]; break;
            case BATCH*SEQ*SEQ: A    = (const float*)d_in[i]; break;
            case FD*FD:         Wk   = (const float*)d_in[i]; break;
            case FD:            bias = (const float*)d_in[i]; break;
            case HEADS*FD*FD:   attn = (const float*)d_in[i]; break;
        }
    }

    const int s1_smem = (TM*S1_STRIDE + FD*FD + TM*S1_STRIDE) * (int)sizeof(float);  // 133120
    const int s2_smem = 6 * TILE_B;                                                   // 208896
    cudaFuncSetAttribute(stage1_kernel, cudaFuncAttributeMaxDynamicSharedMemorySize, s1_smem);
    cudaFuncSetAttribute(stage2_kernel, cudaFuncAttributeMaxDynamicSharedMemorySize, s2_smem);

    stage1_kernel<<<BATCH*(SEQ/TM), 256, s1_smem>>>(X, Wk, bias, attn);
    stage2_kernel<<<BATCH*(SEQ/128)*2, 256, s2_smem>>>(A);   // 128 CTAs
    combine_kernel<<<BATCH*SEQ*FD/(256*4), 256>>>((const float4*)X, (float4*)d_out);
}

// round 15
// speedup vs baseline: 3.1990x; 1.3487x over previous
#include <cuda_runtime.h>
#include <cuda_bf16.h>
#include <cstdint>
#include <math.h>

#define BATCH 4
#define SEQ   2048
#define FD    128
#define HEADS 4
#define TM    64
#define S1_STRIDE 132

#define XS     272            // smem row stride bytes: 8-row ldmatrix groups hit banks 0-3,4-7,... conflict-free
#define TILE_B (128*XS)       // 34816 B per 128x128 bf16 tile

// ---------------- scratch (__device__ globals; no allocs allowed) ----------------
__device__ __nv_bfloat16 g_Xphi[BATCH*SEQ*FD];
__device__ __nv_bfloat16 g_Xplo[BATCH*SEQ*FD];
__device__ __nv_bfloat16 g_Qhi [BATCH*HEADS*SEQ*FD];
__device__ __nv_bfloat16 g_Qlo [BATCH*HEADS*SEQ*FD];
__device__ float g_Opart[2*BATCH*SEQ*FD];            // [pair][b][n][d]

__device__ __forceinline__ uint32_t smem_to_u32(const void* p) {
    uint32_t a;
    asm("{ .reg .u64 t; cvta.to.shared.u64 t, %1; cvt.u32.u64 %0, t; }" : "=r"(a) : "l"(p));
    return a;
}

#define LDSM4(r, addr) \
    asm volatile("ldmatrix.sync.aligned.m8n8.x4.shared.b16 {%0,%1,%2,%3}, [%4];" \
        : "=r"((r)[0]), "=r"((r)[1]), "=r"((r)[2]), "=r"((r)[3]) : "r"(addr))

#define LDSM4T(r, addr) \
    asm volatile("ldmatrix.sync.aligned.m8n8.x4.trans.shared.b16 {%0,%1,%2,%3}, [%4];" \
        : "=r"((r)[0]), "=r"((r)[1]), "=r"((r)[2]), "=r"((r)[3]) : "r"(addr))

#define MMA(c, a, b0_, b1_) \
    asm volatile("mma.sync.aligned.m16n8k16.row.col.f32.bf16.bf16.f32 " \
        "{%0,%1,%2,%3}, {%4,%5,%6,%7}, {%8,%9}, {%0,%1,%2,%3};" \
        : "+f"((c)[0]), "+f"((c)[1]), "+f"((c)[2]), "+f"((c)[3]) \
        : "r"((a)[0]), "r"((a)[1]), "r"((a)[2]), "r"((a)[3]), "r"(b0_), "r"(b1_))

#define CP16(dst, src) \
    asm volatile("cp.async.ca.shared.global [%0], [%1], 16;" :: "r"(dst), "l"(src))
#define CP_COMMIT() asm volatile("cp.async.commit_group;" ::: "memory")

__device__ __forceinline__ void split_bf16(float v, __nv_bfloat16& hi, __nv_bfloat16& lo) {
    hi = __float2bfloat16(v);
    lo = __float2bfloat16(v - __bfloat162float(hi));
}
__device__ __forceinline__ uint32_t pack2(__nv_bfloat16 a, __nv_bfloat16 b) {
    return (uint32_t)__bfloat16_as_ushort(a) | ((uint32_t)__bfloat16_as_ushort(b) << 16);
}
// tanh via MUFU: 1 - 2/(1+e^{2x}); abs err ~1e-6, correct limits at +-inf
__device__ __forceinline__ float tanh_fast(float x) {
    float e = __expf(x + x);
    return 1.0f - __fdividef(2.0f, e + 1.0f);
}

// gmem [128 x FD] bf16 -> smem padded rows (XS bytes), via cp.async
__device__ __forceinline__ void cp_tile(uint32_t dst, const __nv_bfloat16* __restrict__ src, int t) {
#pragma unroll
    for (int i = 0; i < 8; i++) {
        int idx = t + i*256;
        int r = idx >> 4, c = idx & 15;
        CP16(dst + r*XS + c*16, src + (size_t)r*FD + c*8);
    }
}

// ---------------- Stage 1 (FFMA): Xp = X@W + b; Q_h = Xp@attn_h; emit bf16 splits ----------------
__device__ __forceinline__ void gemm_tile_64x128(
    const float* __restrict__ Asrc, const float* __restrict__ Wsrc,
    int ty, int tx, float acc[4][8])
{
#pragma unroll
    for (int i = 0; i < 4; i++)
#pragma unroll
        for (int jj = 0; jj < 8; jj++) acc[i][jj] = 0.f;
#pragma unroll 2
    for (int k = 0; k < FD; k += 4) {
        float a[4][4];
#pragma unroll
        for (int i = 0; i < 4; i++) {
            float4 v = *(const float4*)(Asrc + (4*ty + i)*S1_STRIDE + k);
            a[i][0] = v.x; a[i][1] = v.y; a[i][2] = v.z; a[i][3] = v.w;
        }
#pragma unroll
        for (int kk = 0; kk < 4; kk++) {
            float w[8];
#pragma unroll
            for (int jj = 0; jj < 8; jj++) w[jj] = Wsrc[(k + kk)*FD + tx + 16*jj];
#pragma unroll
            for (int i = 0; i < 4; i++)
#pragma unroll
                for (int jj = 0; jj < 8; jj++)
                    acc[i][jj] = fmaf(a[i][kk], w[jj], acc[i][jj]);
        }
    }
}

extern "C" __global__ void __launch_bounds__(256, 1)
stage1_kernel(const float* __restrict__ X, const float* __restrict__ Wk,
              const float* __restrict__ bias, const float* __restrict__ attn)
{
    extern __shared__ float sm1[];
    float* Xs  = sm1;
    float* Ws  = Xs + TM*S1_STRIDE;
    float* Xps = Ws + FD*FD;

    const int t  = threadIdx.x;
    const int b  = blockIdx.x >> 5;
    const int n0 = (blockIdx.x & 31) * TM;
    const int tx = t & 15, ty = t >> 4;

    {
        const float4* src = (const float4*)(X + (size_t)(b*SEQ + n0)*FD);
#pragma unroll
        for (int i = 0; i < 8; i++) {
            int idx = t + i*256;
            int r = idx >> 5, c4 = idx & 31;
            *(float4*)(Xs + r*S1_STRIDE + 4*c4) = src[idx];
        }
    }
    {
        const float4* src = (const float4*)Wk;
#pragma unroll
        for (int i = 0; i < 16; i++) ((float4*)Ws)[t + i*256] = src[t + i*256];
    }
    __syncthreads();

    float acc[4][8];
    gemm_tile_64x128(Xs, Ws, ty, tx, acc);

    float bv[8];
#pragma unroll
    for (int jj = 0; jj < 8; jj++) bv[jj] = bias[tx + 16*jj];

#pragma unroll
    for (int i = 0; i < 4; i++) {
        int r = 4*ty + i, n = n0 + r;
#pragma unroll
        for (int jj = 0; jj < 8; jj++) {
            float v = acc[i][jj] + bv[jj];
            int d = tx + 16*jj;
            Xps[r*S1_STRIDE + d] = v;
            __nv_bfloat16 hi, lo; split_bf16(v, hi, lo);
            size_t gi = (size_t)(b*SEQ + n)*FD + d;
            g_Xphi[gi] = hi; g_Xplo[gi] = lo;
        }
    }

    for (int h = 0; h < HEADS; h++) {
        __syncthreads();
        const float4* src = (const float4*)(attn + (size_t)h*FD*FD);
#pragma unroll
        for (int i = 0; i < 16; i++) ((float4*)Ws)[t + i*256] = src[t + i*256];
        __syncthreads();

        float qv[4][8];
        gemm_tile_64x128(Xps, Ws, ty, tx, qv);
#pragma unroll
        for (int i = 0; i < 4; i++) {
            int n = n0 + 4*ty + i;
#pragma unroll
            for (int jj = 0; jj < 8; jj++) {
                int d = tx + 16*jj;
                __nv_bfloat16 hi, lo; split_bf16(qv[i][jj], hi, lo);
                size_t gi = ((size_t)(b*HEADS + h)*SEQ + n)*FD + d;
                g_Qhi[gi] = hi; g_Qlo[gi] = lo;
            }
        }
    }
}

// ---------------- Stage 2: register-resident Am, trans-ldmatrix O-GEMM, cp.async pipeline ----------
// grid = 128 CTAs (4b x 16 ntiles x 2 head-pairs), 256 threads, 204KB smem.
// Warp w owns n-rows 16w..16w+15 of the 128-row tile, full m/d width.
extern "C" __global__ void __launch_bounds__(256, 1)
stage2_kernel(const float* __restrict__ Aadj)
{
    extern __shared__ char sm[];
    const int t = threadIdx.x, w = t >> 5, lane = t & 31;
    const int g = lane >> 2, q = lane & 3;
    const int pair = blockIdx.x & 1;
    const int bnt  = blockIdx.x >> 1;
    const int b    = bnt >> 4;
    const int n0   = (bnt & 15) << 7;

    const uint32_t usm  = smem_to_u32(sm);
    const uint32_t uQhi = usm, uQlo = usm + TILE_B;
    const uint32_t uXpB = usm + 2*TILE_B;          // 2 buffers x (hi, lo)

    const int tr = lane & 7, tg = lane >> 3;
    // A-frag / trans-B per-lane offset: subs (r0-7,c0-7),(r8-15,c0-7),(r0-7,c8-15),(r8-15,c8-15)
    const int foff = (tr + ((tg & 1) << 3)) * XS + (((tg >> 1) & 1) << 4);
    // non-trans B per-lane offset: subs (r0-7,k0-7),(r0-7,k8-15),(r8-15,k0-7),(r8-15,k8-15)
    const int boff = (tr + (((tg >> 1) & 1) << 3)) * XS + ((tg & 1) << 4);

    const uint32_t aQhi = uQhi + (16*w)*XS + foff;
    const uint32_t aQlo = uQlo + (16*w)*XS + foff;

    float O[16][4];
#pragma unroll
    for (int nt = 0; nt < 16; nt++)
#pragma unroll
        for (int c = 0; c < 4; c++) O[nt][c] = 0.f;

    // prologue: Q(head pair*2) + Xp tile0 -> buf0, one group
    cp_tile(uQhi, g_Qhi + ((size_t)(b*HEADS + pair*2)*SEQ + n0)*FD, t);
    cp_tile(uQlo, g_Qlo + ((size_t)(b*HEADS + pair*2)*SEQ + n0)*FD, t);
    cp_tile(uXpB,          g_Xphi + (size_t)(b*SEQ)*FD, t);
    cp_tile(uXpB + TILE_B, g_Xplo + (size_t)(b*SEQ)*FD, t);
    CP_COMMIT();

#pragma unroll 1
    for (int r = 0; r < 32; r++) {
        const int mt = r & 15;
        const int m0 = mt << 7;

        __syncthreads();   // all warps done with round r-1 (frees buf[(r+1)&1] and, at r==16, sQ)
        if (r == 16) {
            cp_tile(uQhi, g_Qhi + ((size_t)(b*HEADS + pair*2 + 1)*SEQ + n0)*FD, t);
            cp_tile(uQlo, g_Qlo + ((size_t)(b*HEADS + pair*2 + 1)*SEQ + n0)*FD, t);
            CP_COMMIT();
        }
        if (r < 31) {
            const int nmt = (r + 1) & 15;
            const uint32_t nb = uXpB + (uint32_t)((r + 1) & 1) * 2 * TILE_B;
            cp_tile(nb,          g_Xphi + (size_t)(b*SEQ + (nmt << 7))*FD, t);
            cp_tile(nb + TILE_B, g_Xplo + (size_t)(b*SEQ + (nmt << 7))*FD, t);
            CP_COMMIT();
            asm volatile("cp.async.wait_group 1;" ::: "memory");
        } else {
            asm volatile("cp.async.wait_group 0;" ::: "memory");
        }
        __syncthreads();   // current buffer visible to all warps

        const uint32_t uXhi = uXpB + (uint32_t)(r & 1) * 2 * TILE_B;
        const uint32_t uXlo = uXhi + TILE_B;
        const uint32_t bShi = uXhi + boff;   // S-GEMM B (non-trans), rows = m
        const uint32_t bSlo = uXlo + boff;
        const uint32_t bThi = uXhi + foff;   // O-GEMM B (trans), rows = m, cols = d
        const uint32_t bTlo = uXlo + foff;

        // ---- S-GEMM: S[16n x 128m] = Q[16n x 128k] . Xp[128m x 128k]^T, 3-term bf16 ----
        float S[16][4];
#pragma unroll
        for (int nt = 0; nt < 16; nt++)
#pragma unroll
            for (int c = 0; c < 4; c++) S[nt][c] = 0.f;

#pragma unroll
        for (int kc = 0; kc < 8; kc++) {
            uint32_t ah[4], al[4];
            LDSM4(ah, aQhi + kc*32);
            LDSM4(al, aQlo + kc*32);
#pragma unroll
            for (int np = 0; np < 8; np++) {
                uint32_t bh[4], bl[4];
                LDSM4(bh, bShi + np*16*XS + kc*32);
                LDSM4(bl, bSlo + np*16*XS + kc*32);
                MMA(S[2*np],   ah, bh[0], bh[1]);
                MMA(S[2*np+1], ah, bh[2], bh[3]);
                MMA(S[2*np],   al, bh[0], bh[1]);
                MMA(S[2*np+1], al, bh[2], bh[3]);
                MMA(S[2*np],   ah, bl[0], bl[1]);
                MMA(S[2*np+1], ah, bl[2], bl[3]);
            }
        }

        // ---- Am = tanh(A .* S), bf16 hi/lo packed in-place (register-resident) ----
        {
            const float* ar0 = Aadj + ((size_t)(b*SEQ + n0 + 16*w + g))*SEQ + m0 + 2*q;
            const float* ar1 = ar0 + (size_t)8*SEQ;
#pragma unroll
            for (int nt = 0; nt < 16; nt++) {
                float2 a01 = *(const float2*)(ar0 + 8*nt);
                float2 a23 = *(const float2*)(ar1 + 8*nt);
                float v0 = tanh_fast(a01.x * S[nt][0]);
                float v1 = tanh_fast(a01.y * S[nt][1]);
                float v2 = tanh_fast(a23.x * S[nt][2]);
                float v3 = tanh_fast(a23.y * S[nt][3]);
                __nv_bfloat16 h0, l0, h1, l1, h2, l2, h3, l3;
                split_bf16(v0, h0, l0); split_bf16(v1, h1, l1);
                split_bf16(v2, h2, l2); split_bf16(v3, h3, l3);
                S[nt][0] = __uint_as_float(pack2(h0, h1));   // hi, row g
                S[nt][1] = __uint_as_float(pack2(l0, l1));   // lo, row g
                S[nt][2] = __uint_as_float(pack2(h2, h3));   // hi, row g+8
                S[nt][3] = __uint_as_float(pack2(l2, l3));   // lo, row g+8
            }
        }

        // ---- O-GEMM: O[16n x 128d] += Am[16n x 128m] . Xp[128m x 128d], A from regs, B trans ----
#pragma unroll
        for (int kc = 0; kc < 8; kc++) {
            uint32_t ahi[4], alo[4];
            ahi[0] = __float_as_uint(S[2*kc][0]);   alo[0] = __float_as_uint(S[2*kc][1]);
            ahi[1] = __float_as_uint(S[2*kc][2]);   alo[1] = __float_as_uint(S[2*kc][3]);
            ahi[2] = __float_as_uint(S[2*kc+1][0]); alo[2] = __float_as_uint(S[2*kc+1][1]);
            ahi[3] = __float_as_uint(S[2*kc+1][2]); alo[3] = __float_as_uint(S[2*kc+1][3]);
#pragma unroll
            for (int np = 0; np < 8; np++) {
                uint32_t th[4], tl[4];
                LDSM4T(th, bThi + kc*16*XS + np*32);
                LDSM4T(tl, bTlo + kc*16*XS + np*32);
                MMA(O[2*np],   ahi, th[0], th[1]);
                MMA(O[2*np+1], ahi, th[2], th[3]);
                MMA(O[2*np],   alo, th[0], th[1]);
                MMA(O[2*np+1], alo, th[2], th[3]);
                MMA(O[2*np],   ahi, tl[0], tl[1]);
                MMA(O[2*np+1], ahi, tl[2], tl[3]);
            }
        }
    }

    // ---- epilogue: dump O partial (fp32) ----
    float* dst = g_Opart + (size_t)pair*BATCH*SEQ*FD
               + ((size_t)(b*SEQ) + n0 + 16*w + g)*FD;
#pragma unroll
    for (int ng = 0; ng < 16; ng++) {
        *(float2*)(dst + 8*ng + 2*q)          = make_float2(O[ng][0], O[ng][1]);
        *(float2*)(dst + 8*FD + 8*ng + 2*q)   = make_float2(O[ng][2], O[ng][3]);
    }
}

// ---------------- combine: mean over heads, relu, skip, relu ----------------
extern "C" __global__ void __launch_bounds__(256, 1)
combine_kernel(const float4* __restrict__ X, float4* __restrict__ out)
{
    const int i = blockIdx.x * 256 + threadIdx.x;
    const float4* O0 = (const float4*)g_Opart;
    const float4* O1 = O0 + (BATCH*SEQ*FD/4);
    float4 a = O0[i], c = O1[i], x = X[i], r;
    r.x = fmaxf(fmaxf((a.x + c.x) * 0.25f, 0.f) + x.x, 0.f);
    r.y = fmaxf(fmaxf((a.y + c.y) * 0.25f, 0.f) + x.y, 0.f);
    r.z = fmaxf(fmaxf((a.z + c.z) * 0.25f, 0.f) + x.z, 0.f);
    r.w = fmaxf(fmaxf((a.w + c.w) * 0.25f, 0.f) + x.w, 0.f);
    out[i] = r;
}

extern "C" void kernel_launch(void* const* d_in, const int* in_sizes, int n_in,
                              void* d_out, int out_size)
{
    (void)out_size;
    const float *X = nullptr, *A = nullptr, *Wk = nullptr, *bias = nullptr, *attn = nullptr;
    for (int i = 0; i < n_in; i++) {
        switch (in_sizes[i]) {
            case BATCH*SEQ*FD:  X    = (const float*)d_in[i]; break;
            case BATCH*SEQ*SEQ: A    = (const float*)d_in[i]; break;
            case FD*FD:         Wk   = (const float*)d_in[i]; break;
            case FD:            bias = (const float*)d_in[i]; break;
            case HEADS*FD*FD:   attn = (const float*)d_in[i]; break;
        }
    }

    const int s1_smem = (TM*S1_STRIDE + FD*FD + TM*S1_STRIDE) * (int)sizeof(float);  // 133120
    const int s2_smem = 6 * TILE_B;                                                   // 208896
    cudaFuncSetAttribute(stage1_kernel, cudaFuncAttributeMaxDynamicSharedMemorySize, s1_smem);
    cudaFuncSetAttribute(stage2_kernel, cudaFuncAttributeMaxDynamicSharedMemorySize, s2_smem);

    stage1_kernel<<<BATCH*(SEQ/TM), 256, s1_smem>>>(X, Wk, bias, attn);
    stage2_kernel<<<BATCH*(SEQ/128)*2, 256, s2_smem>>>(A);   // 128 CTAs
    combine_kernel<<<BATCH*SEQ*FD/(256*4), 256>>>((const float4*)X, (float4*)d_out);
}

// round 16
// speedup vs baseline: 4.1346x; 1.2925x over previous
#include <cuda_runtime.h>
#include <cuda_fp16.h>
#include <cstdint>
#include <math.h>

#define BATCH 4
#define SEQ   2048
#define FD    128
#define HEADS 4
#define TM    64
#define S1_STRIDE 132

#define XS     272            // smem row stride bytes: conflict-free ldmatrix
#define TILE_B (128*XS)       // 34816 B per 128x128 fp16 tile

// ---------------- scratch (__device__ globals; no allocs allowed) ----------------
__device__ __half g_Xph[BATCH*SEQ*FD];               // Xp, single fp16 (B operand both GEMMs)
__device__ __half g_Qhh[BATCH*HEADS*SEQ*FD];         // Q hi
__device__ __half g_Qhl[BATCH*HEADS*SEQ*FD];         // Q lo (fp16 residual)
__device__ float g_Opart[2*BATCH*SEQ*FD];            // [pair][b][n][d]

__device__ __forceinline__ uint32_t smem_to_u32(const void* p) {
    uint32_t a;
    asm("{ .reg .u64 t; cvta.to.shared.u64 t, %1; cvt.u32.u64 %0, t; }" : "=r"(a) : "l"(p));
    return a;
}

#define LDSM4(r, addr) \
    asm volatile("ldmatrix.sync.aligned.m8n8.x4.shared.b16 {%0,%1,%2,%3}, [%4];" \
        : "=r"((r)[0]), "=r"((r)[1]), "=r"((r)[2]), "=r"((r)[3]) : "r"(addr))

#define LDSM4T(r, addr) \
    asm volatile("ldmatrix.sync.aligned.m8n8.x4.trans.shared.b16 {%0,%1,%2,%3}, [%4];" \
        : "=r"((r)[0]), "=r"((r)[1]), "=r"((r)[2]), "=r"((r)[3]) : "r"(addr))

#define MMA(c, a, b0_, b1_) \
    asm volatile("mma.sync.aligned.m16n8k16.row.col.f32.f16.f16.f32 " \
        "{%0,%1,%2,%3}, {%4,%5,%6,%7}, {%8,%9}, {%0,%1,%2,%3};" \
        : "+f"((c)[0]), "+f"((c)[1]), "+f"((c)[2]), "+f"((c)[3]) \
        : "r"((a)[0]), "r"((a)[1]), "r"((a)[2]), "r"((a)[3]), "r"(b0_), "r"(b1_))

#define CP16(dst, src) \
    asm volatile("cp.async.ca.shared.global [%0], [%1], 16;" :: "r"(dst), "l"(src))
#define CP_COMMIT() asm volatile("cp.async.commit_group;" ::: "memory")

__device__ __forceinline__ void split_f16(float v, __half& hi, __half& lo) {
    hi = __float2half_rn(v);
    lo = __float2half_rn(v - __half2float(hi));
}
__device__ __forceinline__ uint32_t pack2h(__half a, __half b) {
    return (uint32_t)__half_as_ushort(a) | ((uint32_t)__half_as_ushort(b) << 16);
}
// tanh via MUFU: 1 - 2/(1+e^{2x}); abs err ~1e-6, correct limits at +-inf
__device__ __forceinline__ float tanh_fast(float x) {
    float e = __expf(x + x);
    return 1.0f - __fdividef(2.0f, e + 1.0f);
}

// gmem [128 x FD] fp16 -> smem padded rows (XS bytes), via cp.async
__device__ __forceinline__ void cp_tile(uint32_t dst, const __half* __restrict__ src, int t) {
#pragma unroll
    for (int i = 0; i < 8; i++) {
        int idx = t + i*256;
        int r = idx >> 4, c = idx & 15;
        CP16(dst + r*XS + c*16, src + (size_t)r*FD + c*8);
    }
}

// ---------------- Stage 1 (FFMA): Xp = X@W + b; Q_h = Xp@attn_h; emit fp16 ----------------
__device__ __forceinline__ void gemm_tile_64x128(
    const float* __restrict__ Asrc, const float* __restrict__ Wsrc,
    int ty, int tx, float acc[4][8])
{
#pragma unroll
    for (int i = 0; i < 4; i++)
#pragma unroll
        for (int jj = 0; jj < 8; jj++) acc[i][jj] = 0.f;
#pragma unroll 2
    for (int k = 0; k < FD; k += 4) {
        float a[4][4];
#pragma unroll
        for (int i = 0; i < 4; i++) {
            float4 v = *(const float4*)(Asrc + (4*ty + i)*S1_STRIDE + k);
            a[i][0] = v.x; a[i][1] = v.y; a[i][2] = v.z; a[i][3] = v.w;
        }
#pragma unroll
        for (int kk = 0; kk < 4; kk++) {
            float w[8];
#pragma unroll
            for (int jj = 0; jj < 8; jj++) w[jj] = Wsrc[(k + kk)*FD + tx + 16*jj];
#pragma unroll
            for (int i = 0; i < 4; i++)
#pragma unroll
                for (int jj = 0; jj < 8; jj++)
                    acc[i][jj] = fmaf(a[i][kk], w[jj], acc[i][jj]);
        }
    }
}

extern "C" __global__ void __launch_bounds__(256, 1)
stage1_kernel(const float* __restrict__ X, const float* __restrict__ Wk,
              const float* __restrict__ bias, const float* __restrict__ attn)
{
    extern __shared__ float sm1[];
    float* Xs  = sm1;
    float* Ws  = Xs + TM*S1_STRIDE;
    float* Xps = Ws + FD*FD;

    const int t  = threadIdx.x;
    const int b  = blockIdx.x >> 5;
    const int n0 = (blockIdx.x & 31) * TM;
    const int tx = t & 15, ty = t >> 4;

    {
        const float4* src = (const float4*)(X + (size_t)(b*SEQ + n0)*FD);
#pragma unroll
        for (int i = 0; i < 8; i++) {
            int idx = t + i*256;
            int r = idx >> 5, c4 = idx & 31;
            *(float4*)(Xs + r*S1_STRIDE + 4*c4) = src[idx];
        }
    }
    {
        const float4* src = (const float4*)Wk;
#pragma unroll
        for (int i = 0; i < 16; i++) ((float4*)Ws)[t + i*256] = src[t + i*256];
    }
    __syncthreads();

    float acc[4][8];
    gemm_tile_64x128(Xs, Ws, ty, tx, acc);

    float bv[8];
#pragma unroll
    for (int jj = 0; jj < 8; jj++) bv[jj] = bias[tx + 16*jj];

#pragma unroll
    for (int i = 0; i < 4; i++) {
        int r = 4*ty + i, n = n0 + r;
#pragma unroll
        for (int jj = 0; jj < 8; jj++) {
            float v = acc[i][jj] + bv[jj];
            int d = tx + 16*jj;
            Xps[r*S1_STRIDE + d] = v;
            g_Xph[(size_t)(b*SEQ + n)*FD + d] = __float2half_rn(v);
        }
    }

    for (int h = 0; h < HEADS; h++) {
        __syncthreads();
        const float4* src = (const float4*)(attn + (size_t)h*FD*FD);
#pragma unroll
        for (int i = 0; i < 16; i++) ((float4*)Ws)[t + i*256] = src[t + i*256];
        __syncthreads();

        float qv[4][8];
        gemm_tile_64x128(Xps, Ws, ty, tx, qv);
#pragma unroll
        for (int i = 0; i < 4; i++) {
            int n = n0 + 4*ty + i;
#pragma unroll
            for (int jj = 0; jj < 8; jj++) {
                int d = tx + 16*jj;
                __half hi, lo; split_f16(qv[i][jj], hi, lo);
                size_t gi = ((size_t)(b*HEADS + h)*SEQ + n)*FD + d;
                g_Qhh[gi] = hi; g_Qhl[gi] = lo;
            }
        }
    }
}

// ---------------- Stage 2: fp16 2-pass, register-resident Am, cp.async pipeline ----------
// grid = 128 CTAs (4b x 16 ntiles x 2 head-pairs), 256 threads, 139KB smem.
// Warp w owns n-rows 16w..16w+15 of the 128-row tile, full m/d width.
extern "C" __global__ void __launch_bounds__(256, 1)
stage2_kernel(const float* __restrict__ Aadj)
{
    extern __shared__ char sm[];
    const int t = threadIdx.x, w = t >> 5, lane = t & 31;
    const int g = lane >> 2, q = lane & 3;
    const int pair = blockIdx.x & 1;
    const int bnt  = blockIdx.x >> 1;
    const int b    = bnt >> 4;
    const int n0   = (bnt & 15) << 7;

    const uint32_t usm  = smem_to_u32(sm);
    const uint32_t uQhi = usm, uQlo = usm + TILE_B;
    const uint32_t uXpB = usm + 2*TILE_B;          // 2 buffers x 1 tile

    const int tr = lane & 7, tg = lane >> 3;
    // A-frag / trans-B per-lane offset
    const int foff = (tr + ((tg & 1) << 3)) * XS + (((tg >> 1) & 1) << 4);
    // non-trans B per-lane offset
    const int boff = (tr + (((tg >> 1) & 1) << 3)) * XS + ((tg & 1) << 4);

    const uint32_t aQhi = uQhi + (16*w)*XS + foff;
    const uint32_t aQlo = uQlo + (16*w)*XS + foff;

    float O[16][4];
#pragma unroll
    for (int nt = 0; nt < 16; nt++)
#pragma unroll
        for (int c = 0; c < 4; c++) O[nt][c] = 0.f;

    // prologue: Q(head pair*2) hi/lo + Xp tile0 -> buf0, one group
    cp_tile(uQhi, g_Qhh + ((size_t)(b*HEADS + pair*2)*SEQ + n0)*FD, t);
    cp_tile(uQlo, g_Qhl + ((size_t)(b*HEADS + pair*2)*SEQ + n0)*FD, t);
    cp_tile(uXpB, g_Xph + (size_t)(b*SEQ)*FD, t);
    CP_COMMIT();

#pragma unroll 1
    for (int r = 0; r < 32; r++) {
        const int mt = r & 15;
        const int m0 = mt << 7;

        __syncthreads();   // all warps done with round r-1 (frees buf[(r+1)&1] and, at r==16, sQ)
        if (r == 16) {
            cp_tile(uQhi, g_Qhh + ((size_t)(b*HEADS + pair*2 + 1)*SEQ + n0)*FD, t);
            cp_tile(uQlo, g_Qhl + ((size_t)(b*HEADS + pair*2 + 1)*SEQ + n0)*FD, t);
            CP_COMMIT();
        }
        if (r < 31) {
            const int nmt = (r + 1) & 15;
            const uint32_t nb = uXpB + (uint32_t)((r + 1) & 1) * TILE_B;
            cp_tile(nb, g_Xph + (size_t)(b*SEQ + (nmt << 7))*FD, t);
            CP_COMMIT();
            asm volatile("cp.async.wait_group 1;" ::: "memory");
        } else {
            asm volatile("cp.async.wait_group 0;" ::: "memory");
        }
        __syncthreads();   // current buffer visible to all warps

        const uint32_t uX  = uXpB + (uint32_t)(r & 1) * TILE_B;
        const uint32_t bS  = uX + boff;   // S-GEMM B (non-trans), rows = m
        const uint32_t bT  = uX + foff;   // O-GEMM B (trans), rows = m, cols = d

        // ---- S-GEMM: S[16n x 128m] = (Qh+Ql)[16n x 128k] . Xp16[128m x 128k]^T ----
        float S[16][4];
#pragma unroll
        for (int nt = 0; nt < 16; nt++)
#pragma unroll
            for (int c = 0; c < 4; c++) S[nt][c] = 0.f;

#pragma unroll
        for (int kc = 0; kc < 8; kc++) {
            uint32_t ah[4], al[4];
            LDSM4(ah, aQhi + kc*32);
            LDSM4(al, aQlo + kc*32);
#pragma unroll
            for (int np = 0; np < 8; np++) {
                uint32_t bh[4];
                LDSM4(bh, bS + np*16*XS + kc*32);
                MMA(S[2*np],   ah, bh[0], bh[1]);
                MMA(S[2*np+1], ah, bh[2], bh[3]);
                MMA(S[2*np],   al, bh[0], bh[1]);
                MMA(S[2*np+1], al, bh[2], bh[3]);
            }
        }

        // ---- Am = tanh(A .* S), fp16 hi/lo packed in-place (register-resident) ----
        {
            const float* ar0 = Aadj + ((size_t)(b*SEQ + n0 + 16*w + g))*SEQ + m0 + 2*q;
            const float* ar1 = ar0 + (size_t)8*SEQ;
#pragma unroll
            for (int nt = 0; nt < 16; nt++) {
                float2 a01 = *(const float2*)(ar0 + 8*nt);
                float2 a23 = *(const float2*)(ar1 + 8*nt);
                float v0 = tanh_fast(a01.x * S[nt][0]);
                float v1 = tanh_fast(a01.y * S[nt][1]);
                float v2 = tanh_fast(a23.x * S[nt][2]);
                float v3 = tanh_fast(a23.y * S[nt][3]);
                __half h0, l0, h1, l1, h2, l2, h3, l3;
                split_f16(v0, h0, l0); split_f16(v1, h1, l1);
                split_f16(v2, h2, l2); split_f16(v3, h3, l3);
                S[nt][0] = __uint_as_float(pack2h(h0, h1));   // hi, row g
                S[nt][1] = __uint_as_float(pack2h(l0, l1));   // lo, row g
                S[nt][2] = __uint_as_float(pack2h(h2, h3));   // hi, row g+8
                S[nt][3] = __uint_as_float(pack2h(l2, l3));   // lo, row g+8
            }
        }

        // ---- O-GEMM: O[16n x 128d] += (AmH+AmL)[16n x 128m] . Xp16[128m x 128d] ----
#pragma unroll
        for (int kc = 0; kc < 8; kc++) {
            uint32_t ahi[4], alo[4];
            ahi[0] = __float_as_uint(S[2*kc][0]);   alo[0] = __float_as_uint(S[2*kc][1]);
            ahi[1] = __float_as_uint(S[2*kc][2]);   alo[1] = __float_as_uint(S[2*kc][3]);
            ahi[2] = __float_as_uint(S[2*kc+1][0]); alo[2] = __float_as_uint(S[2*kc+1][1]);
            ahi[3] = __float_as_uint(S[2*kc+1][2]); alo[3] = __float_as_uint(S[2*kc+1][3]);
#pragma unroll
            for (int np = 0; np < 8; np++) {
                uint32_t th[4];
                LDSM4T(th, bT + kc*16*XS + np*32);
                MMA(O[2*np],   ahi, th[0], th[1]);
                MMA(O[2*np+1], ahi, th[2], th[3]);
                MMA(O[2*np],   alo, th[0], th[1]);
                MMA(O[2*np+1], alo, th[2], th[3]);
            }
        }
    }

    // ---- epilogue: dump O partial (fp32) ----
    float* dst = g_Opart + (size_t)pair*BATCH*SEQ*FD
               + ((size_t)(b*SEQ) + n0 + 16*w + g)*FD;
#pragma unroll
    for (int ng = 0; ng < 16; ng++) {
        *(float2*)(dst + 8*ng + 2*q)          = make_float2(O[ng][0], O[ng][1]);
        *(float2*)(dst + 8*FD + 8*ng + 2*q)   = make_float2(O[ng][2], O[ng][3]);
    }
}

// ---------------- combine: mean over heads, relu, skip, relu ----------------
extern "C" __global__ void __launch_bounds__(256, 1)
combine_kernel(const float4* __restrict__ X, float4* __restrict__ out)
{
    const int i = blockIdx.x * 256 + threadIdx.x;
    const float4* O0 = (const float4*)g_Opart;
    const float4* O1 = O0 + (BATCH*SEQ*FD/4);
    float4 a = O0[i], c = O1[i], x = X[i], r;
    r.x = fmaxf(fmaxf((a.x + c.x) * 0.25f, 0.f) + x.x, 0.f);
    r.y = fmaxf(fmaxf((a.y + c.y) * 0.25f, 0.f) + x.y, 0.f);
    r.z = fmaxf(fmaxf((a.z + c.z) * 0.25f, 0.f) + x.z, 0.f);
    r.w = fmaxf(fmaxf((a.w + c.w) * 0.25f, 0.f) + x.w, 0.f);
    out[i] = r;
}

extern "C" void kernel_launch(void* const* d_in, const int* in_sizes, int n_in,
                              void* d_out, int out_size)
{
    (void)out_size;
    const float *X = nullptr, *A = nullptr, *Wk = nullptr, *bias = nullptr, *attn = nullptr;
    for (int i = 0; i < n_in; i++) {
        switch (in_sizes[i]) {
            case BATCH*SEQ*FD:  X    = (const float*)d_in[i]; break;
            case BATCH*SEQ*SEQ: A    = (const float*)d_in[i]; break;
            case FD*FD:         Wk   = (const float*)d_in[i]; break;
            case FD:            bias = (const float*)d_in[i]; break;
            case HEADS*FD*FD:   attn = (const float*)d_in[i]; break;
        }
    }

    const int s1_smem = (TM*S1_STRIDE + FD*FD + TM*S1_STRIDE) * (int)sizeof(float);  // 133120
    const int s2_smem = 4 * TILE_B;                                                   // 139264
    cudaFuncSetAttribute(stage1_kernel, cudaFuncAttributeMaxDynamicSharedMemorySize, s1_smem);
    cudaFuncSetAttribute(stage2_kernel, cudaFuncAttributeMaxDynamicSharedMemorySize, s2_smem);

    stage1_kernel<<<BATCH*(SEQ/TM), 256, s1_smem>>>(X, Wk, bias, attn);
    stage2_kernel<<<BATCH*(SEQ/128)*2, 256, s2_smem>>>(A);   // 128 CTAs
    combine_kernel<<<BATCH*SEQ*FD/(256*4), 256>>>((const float4*)X, (float4*)d_out);
}